// round 4
// baseline (speedup 1.0000x reference)
#include <cuda_runtime.h>
#include <math.h>
#include <stdint.h>

static constexpr int SEQ    = 2048;
static constexpr int HIDDEN = 2048;
static constexpr int NHEAD  = 16;
static constexpr int NKV    = 2;
static constexpr int HD     = 256;
static constexpr int QROW   = NHEAD * HD * 2;   // 8192 (query | gate per head)
static constexpr int KROW   = NKV * HD;         // 512
static constexpr int ODIM   = NHEAD * HD;       // 4096
static constexpr float ATTN_SCALE = 0.0625f;    // 256^-0.5

// Scratch (static device memory; no allocations allowed)
__device__ float g_qout[(size_t)SEQ * QROW];            // 64 MB
__device__ float g_kbuf[(size_t)SEQ * KROW];            // 4 MB  [t][kv*256+d]
__device__ float g_vtbuf[(size_t)KROW * SEQ];           // 4 MB  [kv*256+d][t]
__device__ float g_sbuf[(size_t)NHEAD * SEQ * SEQ];     // 256 MB scores/probs
__device__ float g_obuf[(size_t)SEQ * ODIM];            // 32 MB

// ======================= tf32 mma.sync NT GEMM =============================
// C[m,n] = alpha * sum_k A[m,k] * B[n,k]   (both row-major, k contiguous)
// BM=128, BN=128, BK=16.  256 threads = 8 warps as 4(m) x 2(n); warp 32x64.
// SMEM tiles stored in m16n8k8 fragment order with an XOR swizzle that makes
// both the STS scatter (<=2-way) and fragment LDS (conflict-free) cheap.
static constexpr int BM = 128, BN = 128, BK = 16;
static constexpr int ASZ = 2064;   // uint32s per A buffer
static constexpr int BSZ = 2064;   // uint32s per B buffer
static constexpr int SMEM_BYTES = (2 * ASZ + 2 * BSZ) * 4;  // 33024

__device__ __forceinline__ uint32_t f2tf32(float x) {
    uint32_t r;
    asm("cvt.rna.tf32.f32 %0, %1;" : "=r"(r) : "f"(x));
    return r;
}

__device__ __forceinline__ void mma_tf32(float* c, const uint32_t* a, const uint32_t* b) {
    asm volatile(
        "mma.sync.aligned.m16n8k8.row.col.f32.tf32.tf32.f32 "
        "{%0,%1,%2,%3}, {%4,%5,%6,%7}, {%8,%9}, {%0,%1,%2,%3};"
        : "+f"(c[0]), "+f"(c[1]), "+f"(c[2]), "+f"(c[3])
        : "r"(a[0]), "r"(a[1]), "r"(a[2]), "r"(a[3]), "r"(b[0]), "r"(b[1]));
}

__global__ __launch_bounds__(256, 2) void tc_gemm_nt(
    const float* __restrict__ A, const float* __restrict__ B, float* __restrict__ C,
    int K, int lda, int ldb, int ldc,
    long long batchA, int groupB, long long batchB, long long batchC,
    float alpha, int causal, int truncK,
    const float* __restrict__ G, long long batchG, int ldG)
{
    int m0 = blockIdx.y * BM, n0 = blockIdx.x * BN;
    if (causal && n0 > m0) return;          // fully-masked score tile
    long long z = blockIdx.z;
    A += z * batchA;
    B += (z / groupB) * batchB;
    C += z * batchC;
    if (G) G += z * batchG;
    int kmax = truncK ? min(K, m0 + BM) : K;
    int nk = kmax >> 4;

    extern __shared__ uint32_t smem[];
    uint32_t* As = smem;              // two A buffers
    uint32_t* Bs = smem + 2 * ASZ;    // two B buffers

    int tid = threadIdx.x;
    int lane = tid & 31, wid = tid >> 5;
    int wm = wid >> 1, wn = wid & 1;

    // ---- STS scatter bases (2 float4s per matrix per thread per k-tile) ----
    int aBase[2], aX[2], aRow[2], aCol[2];
    #pragma unroll
    for (int i = 0; i < 2; i++) {
        int f = tid + i * 256;            // 0..511 float4 idx in 128x16 tile
        int r = f >> 2, c4 = f & 3;
        aRow[i] = r; aCol[i] = c4 * 4;
        int s = c4 >> 1, jh = c4 & 1;
        int mt = r >> 4, g = r & 7, jl = (r >> 3) & 1;
        int j = (jh << 1) | jl;
        aX[i] = (g >> 1) & 3;
        aBase[i] = (((s * 8 + mt) * 32) + (g << 2)) * 4 + j + s * 4;
    }
    int bBase[2], bX[2], bRow[2], bCol[2];
    #pragma unroll
    for (int i = 0; i < 2; i++) {
        int f = tid + i * 256;            // 0..511 float4 idx in 128x16 tile
        int n = f >> 2, c4 = f & 3;
        bRow[i] = n; bCol[i] = c4 * 4;
        int s = c4 >> 1, j = c4 & 1;
        int nt = n >> 3;
        bX[i] = ((n >> 2) & 1) << 1;
        bBase[i] = (((s * 16 + nt) * 32) + ((n & 7) << 2)) * 2 + j + s * 4;
    }
    int laneA = lane ^ ((lane >> 3) & 3);
    int laneB = lane ^ (((lane >> 4) & 1) << 1);

    float acc[2][8][4];
    #pragma unroll
    for (int i = 0; i < 2; i++)
        #pragma unroll
        for (int jj = 0; jj < 8; jj++)
            #pragma unroll
            for (int q = 0; q < 4; q++) acc[i][jj][q] = 0.f;

    float4 apre[2], bpre[2];

    auto ldg = [&](int k0) {
        #pragma unroll
        for (int i = 0; i < 2; i++)
            apre[i] = *reinterpret_cast<const float4*>(
                A + (long long)(m0 + aRow[i]) * lda + k0 + aCol[i]);
        #pragma unroll
        for (int i = 0; i < 2; i++)
            bpre[i] = *reinterpret_cast<const float4*>(
                B + (long long)(n0 + bRow[i]) * ldb + k0 + bCol[i]);
    };
    auto sts = [&](int buf) {
        uint32_t* a = As + buf * ASZ;
        #pragma unroll
        for (int i = 0; i < 2; i++) {
            a[aBase[i] + ((0 ^ aX[i]) << 2)] = f2tf32(apre[i].x);
            a[aBase[i] + ((1 ^ aX[i]) << 2)] = f2tf32(apre[i].y);
            a[aBase[i] + ((2 ^ aX[i]) << 2)] = f2tf32(apre[i].z);
            a[aBase[i] + ((3 ^ aX[i]) << 2)] = f2tf32(apre[i].w);
        }
        uint32_t* b = Bs + buf * BSZ;
        #pragma unroll
        for (int i = 0; i < 2; i++) {
            b[bBase[i] + ((0 ^ bX[i]) << 1)] = f2tf32(bpre[i].x);
            b[bBase[i] + ((1 ^ bX[i]) << 1)] = f2tf32(bpre[i].y);
            b[bBase[i] + ((2 ^ bX[i]) << 1)] = f2tf32(bpre[i].z);
            b[bBase[i] + ((3 ^ bX[i]) << 1)] = f2tf32(bpre[i].w);
        }
    };

    ldg(0);
    sts(0);
    __syncthreads();

    int buf = 0;
    for (int kt = 0; kt < nk; kt++) {
        if (kt + 1 < nk) ldg((kt + 1) << 4);

        uint32_t* a = As + buf * ASZ;
        uint32_t* b = Bs + buf * BSZ;
        #pragma unroll
        for (int s = 0; s < 2; s++) {
            uint32_t af[2][4], bf[8][2];
            #pragma unroll
            for (int mtl = 0; mtl < 2; mtl++) {
                uint4 v = *reinterpret_cast<const uint4*>(
                    a + ((s * 8 + wm * 2 + mtl) * 32 + laneA) * 4 + s * 4);
                af[mtl][0] = v.x; af[mtl][1] = v.y; af[mtl][2] = v.z; af[mtl][3] = v.w;
            }
            #pragma unroll
            for (int ntl = 0; ntl < 8; ntl++) {
                uint2 v = *reinterpret_cast<const uint2*>(
                    b + ((s * 16 + wn * 8 + ntl) * 32 + laneB) * 2 + s * 4);
                bf[ntl][0] = v.x; bf[ntl][1] = v.y;
            }
            #pragma unroll
            for (int mtl = 0; mtl < 2; mtl++)
                #pragma unroll
                for (int ntl = 0; ntl < 8; ntl++)
                    mma_tf32(acc[mtl][ntl], af[mtl], bf[ntl]);
        }

        if (kt + 1 < nk) {
            sts(buf ^ 1);
            __syncthreads();
            buf ^= 1;
        }
    }

    // ---- epilogue: direct STG (float2 per fragment row), optional gating ----
    int g = lane >> 2, t2 = (lane & 3) * 2;
    #pragma unroll
    for (int mtl = 0; mtl < 2; mtl++) {
        #pragma unroll
        for (int ntl = 0; ntl < 8; ntl++) {
            long long row = m0 + wm * 32 + mtl * 16 + g;
            int col = n0 + wn * 64 + ntl * 8 + t2;
            float2 v0 = make_float2(acc[mtl][ntl][0] * alpha, acc[mtl][ntl][1] * alpha);
            float2 v1 = make_float2(acc[mtl][ntl][2] * alpha, acc[mtl][ntl][3] * alpha);
            if (G) {
                float2 g0 = *reinterpret_cast<const float2*>(G + row * ldG + col);
                float2 g1 = *reinterpret_cast<const float2*>(G + (row + 8) * ldG + col);
                v0.x *= 1.0f / (1.0f + expf(-g0.x));
                v0.y *= 1.0f / (1.0f + expf(-g0.y));
                v1.x *= 1.0f / (1.0f + expf(-g1.x));
                v1.y *= 1.0f / (1.0f + expf(-g1.y));
            }
            *reinterpret_cast<float2*>(C + row * ldc + col) = v0;
            *reinterpret_cast<float2*>(C + (row + 8) * ldc + col) = v1;
        }
    }
}

// ============================ elementwise kernels ==========================
// Warp-per-row RMSNorm + RoPE. 8 warps/block, one (token, head) row per warp.
__global__ __launch_bounds__(256) void rmsnorm_rope(
    float* __restrict__ x, const float* __restrict__ w,
    const int* __restrict__ pos, int nheads, int rowStride, int headStride)
{
    int wid = threadIdx.x >> 5, lane = threadIdx.x & 31;
    int ridx = blockIdx.x * 8 + wid;
    int t = ridx / nheads, h = ridx - t * nheads;
    float* row = x + (size_t)t * rowStride + (size_t)h * headStride;

    float4 v1 = *reinterpret_cast<const float4*>(row + lane * 4);
    float4 v2 = *reinterpret_cast<const float4*>(row + 128 + lane * 4);
    float s = v1.x * v1.x + v1.y * v1.y + v1.z * v1.z + v1.w * v1.w
            + v2.x * v2.x + v2.y * v2.y + v2.z * v2.z + v2.w * v2.w;
    #pragma unroll
    for (int o = 16; o; o >>= 1) s += __shfl_xor_sync(0xffffffffu, s, o);
    float rinv = rsqrtf(s * (1.0f / 256.0f) + 1e-6f);

    float4 w1 = *reinterpret_cast<const float4*>(w + lane * 4);
    float4 w2 = *reinterpret_cast<const float4*>(w + 128 + lane * 4);
    float y[4] = { v1.x * rinv * (1.0f + w1.x), v1.y * rinv * (1.0f + w1.y),
                   v1.z * rinv * (1.0f + w1.z), v1.w * rinv * (1.0f + w1.w) };
    float y2[4] = { v2.x * rinv * (1.0f + w2.x), v2.y * rinv * (1.0f + w2.y),
                    v2.z * rinv * (1.0f + w2.z), v2.w * rinv * (1.0f + w2.w) };

    // RoPE on cols 0..63 (lanes 0..15); pairs (d, d+32) are 8 lanes apart.
    float oth[4];
    #pragma unroll
    for (int j = 0; j < 4; j++) oth[j] = __shfl_xor_sync(0xffffffffu, y[j], 8);
    if (lane < 16) {
        float p = (float)pos[t];
        #pragma unroll
        for (int j = 0; j < 4; j++) {
            int d = lane * 4 + j;
            int i = d & 31;                    // frequency index
            float inv = expf(-(float)i * (16.118095650958322f / 32.0f));
            float sn, cs;
            sincosf(p * inv, &sn, &cs);
            float x1, x2;
            if (lane < 8) { x1 = y[j]; x2 = oth[j]; y[j] = x1 * cs - x2 * sn; }
            else          { x2 = y[j]; x1 = oth[j]; y[j] = x2 * cs + x1 * sn; }
        }
    }
    *reinterpret_cast<float4*>(row + lane * 4) = make_float4(y[0], y[1], y[2], y[3]);
    *reinterpret_cast<float4*>(row + 128 + lane * 4) =
        make_float4(y2[0], y2[1], y2[2], y2[3]);
}

__global__ __launch_bounds__(256) void softmax_causal(float* __restrict__ S)
{
    int q = blockIdx.x, h = blockIdx.y;
    float* row = S + ((size_t)h * SEQ + q) * (size_t)SEQ;
    int n = q + 1;
    int nw = min(SEQ, ((q >> 7) + 1) << 7);   // PV only reads k < this bound
    int tid = threadIdx.x;

    float vals[SEQ / 256];
    float m = -3.4e38f;
    #pragma unroll
    for (int i = 0; i < SEQ / 256; i++) {
        int k = tid + i * 256;
        float v = (k < n) ? row[k] : -3.4e38f;
        vals[i] = v;
        m = fmaxf(m, v);
    }
    __shared__ float red[8];
    #pragma unroll
    for (int o = 16; o; o >>= 1) m = fmaxf(m, __shfl_xor_sync(0xffffffffu, m, o));
    if ((tid & 31) == 0) red[tid >> 5] = m;
    __syncthreads();
    if (tid < 32) {
        float x = (tid < 8) ? red[tid] : -3.4e38f;
        #pragma unroll
        for (int o = 4; o; o >>= 1) x = fmaxf(x, __shfl_xor_sync(0xffffffffu, x, o));
        if (tid == 0) red[0] = x;
    }
    __syncthreads();
    m = red[0];
    __syncthreads();

    float ssum = 0.f;
    #pragma unroll
    for (int i = 0; i < SEQ / 256; i++) {
        int k = tid + i * 256;
        float e = (k < n) ? expf(vals[i] - m) : 0.f;
        vals[i] = e;
        ssum += e;
    }
    #pragma unroll
    for (int o = 16; o; o >>= 1) ssum += __shfl_xor_sync(0xffffffffu, ssum, o);
    if ((tid & 31) == 0) red[tid >> 5] = ssum;
    __syncthreads();
    if (tid < 32) {
        float x = (tid < 8) ? red[tid] : 0.f;
        #pragma unroll
        for (int o = 4; o; o >>= 1) x += __shfl_xor_sync(0xffffffffu, x, o);
        if (tid == 0) red[0] = x;
    }
    __syncthreads();
    float inv = 1.0f / red[0];
    #pragma unroll
    for (int i = 0; i < SEQ / 256; i++) {
        int k = tid + i * 256;
        if (k < nw) row[k] = vals[i] * inv;   // zeros beyond n, up to PV bound
    }
}

// ============================ host launch ==================================
extern "C" void kernel_launch(void* const* d_in, const int* in_sizes, int n_in,
                              void* d_out, int out_size)
{
    const int*   positions = (const int*)d_in[0];
    const float* hs  = (const float*)d_in[1];
    const float* wq  = (const float*)d_in[2];
    const float* wk  = (const float*)d_in[3];
    const float* wv  = (const float*)d_in[4];
    const float* wo  = (const float*)d_in[5];
    const float* qnw = (const float*)d_in[6];
    const float* knw = (const float*)d_in[7];
    float* out = (float*)d_out;

    float *qout, *kbuf, *vt, *sbuf, *obuf;
    cudaGetSymbolAddress((void**)&qout, g_qout);
    cudaGetSymbolAddress((void**)&kbuf, g_kbuf);
    cudaGetSymbolAddress((void**)&vt,   g_vtbuf);
    cudaGetSymbolAddress((void**)&sbuf, g_sbuf);
    cudaGetSymbolAddress((void**)&obuf, g_obuf);

    cudaFuncSetAttribute(tc_gemm_nt, cudaFuncAttributeMaxDynamicSharedMemorySize,
                         SMEM_BYTES);

    dim3 blk(256);

    // 1) Q projection: qout = hs @ wq^T           [2048 x 8192]
    tc_gemm_nt<<<dim3(QROW / BN, SEQ / BM, 1), blk, SMEM_BYTES>>>(
        hs, wq, qout, HIDDEN, HIDDEN, HIDDEN, QROW, 0, 1, 0, 0, 1.0f, 0, 0,
        nullptr, 0, 0);
    // 2) K projection: kbuf = hs @ wk^T           [2048 x 512]
    tc_gemm_nt<<<dim3(KROW / BN, SEQ / BM, 1), blk, SMEM_BYTES>>>(
        hs, wk, kbuf, HIDDEN, HIDDEN, HIDDEN, KROW, 0, 1, 0, 0, 1.0f, 0, 0,
        nullptr, 0, 0);
    // 3) V^T: vt = wv @ hs^T                      [512 x 2048]
    tc_gemm_nt<<<dim3(SEQ / BN, KROW / BM, 1), blk, SMEM_BYTES>>>(
        wv, hs, vt, HIDDEN, HIDDEN, HIDDEN, SEQ, 0, 1, 0, 0, 1.0f, 0, 0,
        nullptr, 0, 0);

    // 4) RMSNorm + RoPE (in place, warp per row)
    rmsnorm_rope<<<SEQ * NHEAD / 8, 256>>>(qout, qnw, positions, NHEAD, QROW, 2 * HD);
    rmsnorm_rope<<<SEQ * NKV / 8, 256>>>(kbuf, knw, positions, NKV, KROW, HD);

    // 5) Scores: S[h][q][k] = scale * q . k  (causal tile skip)
    tc_gemm_nt<<<dim3(SEQ / BN, SEQ / BM, NHEAD), blk, SMEM_BYTES>>>(
        qout, kbuf, sbuf, HD, QROW, KROW, SEQ,
        /*batchA=*/2 * HD, /*groupB=*/NHEAD / NKV, /*batchB=*/HD,
        /*batchC=*/(long long)SEQ * SEQ, ATTN_SCALE, /*causal=*/1, 0,
        nullptr, 0, 0);

    // 6) Causal softmax (writes only up to the PV truncation bound)
    softmax_causal<<<dim3(SEQ, NHEAD), 256>>>(sbuf);

    // 7) O = P @ V via NT with V^T (K truncated by causality) + fused gate
    tc_gemm_nt<<<dim3(HD / BN, SEQ / BM, NHEAD), blk, SMEM_BYTES>>>(
        sbuf, vt, obuf, SEQ, SEQ, SEQ, ODIM,
        /*batchA=*/(long long)SEQ * SEQ, /*groupB=*/NHEAD / NKV,
        /*batchB=*/(long long)HD * SEQ, /*batchC=*/HD, 1.0f, 0, /*truncK=*/1,
        /*G=*/qout + HD, /*batchG=*/2 * HD, /*ldG=*/QROW);

    // 8) Output projection: out = obuf @ wo^T
    tc_gemm_nt<<<dim3(HIDDEN / BN, SEQ / BM, 1), blk, SMEM_BYTES>>>(
        obuf, wo, out, ODIM, ODIM, ODIM, HIDDEN, 0, 1, 0, 0, 1.0f, 0, 0,
        nullptr, 0, 0);
}

// round 5
// speedup vs baseline: 2.5763x; 2.5763x over previous
#include <cuda_runtime.h>
#include <cuda_fp16.h>
#include <math.h>
#include <stdint.h>

static constexpr int SEQ    = 2048;
static constexpr int HIDDEN = 2048;
static constexpr int NHEAD  = 16;
static constexpr int NKV    = 2;
static constexpr int HD     = 256;
static constexpr int QROW   = NHEAD * HD * 2;   // 8192
static constexpr int KROW   = NKV * HD;         // 512
static constexpr int ODIM   = NHEAD * HD;       // 4096
static constexpr float ATTN_SCALE = 0.0625f;

// ---- scratch (static device memory; no allocations allowed) ----
__device__ __half g_hs_h  [(size_t)SEQ * HIDDEN];
__device__ __half g_wq_h  [(size_t)QROW * HIDDEN];
__device__ __half g_wk_h  [(size_t)KROW * HIDDEN];
__device__ __half g_wv_h  [(size_t)KROW * HIDDEN];
__device__ __half g_wo_h  [(size_t)HIDDEN * ODIM];
__device__ __half g_qout_h[(size_t)SEQ * QROW];
__device__ __half g_kbuf_h[(size_t)SEQ * KROW];
__device__ __half g_vt_h  [(size_t)KROW * SEQ];
__device__ __half g_obuf_h[(size_t)SEQ * ODIM];
__device__ float  g_sbuf  [(size_t)NHEAD * SEQ * SEQ];  // scores f32; probs fp16 alias

// ============================ asm helpers ==================================
__device__ __forceinline__ uint32_t smem_u32(const void* p) {
    uint32_t a;
    asm("{ .reg .u64 t; cvta.to.shared.u64 t, %1; cvt.u32.u64 %0, t; }" : "=r"(a) : "l"(p));
    return a;
}
#define CP_ASYNC16(dst, src) \
    asm volatile("cp.async.cg.shared.global [%0], [%1], 16;" :: "r"(dst), "l"(src))
#define CP_COMMIT() asm volatile("cp.async.commit_group;")
#define CP_WAIT(n)  asm volatile("cp.async.wait_group %0;" :: "n"(n))

__device__ __forceinline__ void ldm_x4(uint32_t* r, uint32_t addr) {
    asm volatile("ldmatrix.sync.aligned.m8n8.x4.shared.b16 {%0,%1,%2,%3}, [%4];"
                 : "=r"(r[0]), "=r"(r[1]), "=r"(r[2]), "=r"(r[3]) : "r"(addr));
}
__device__ __forceinline__ void mma_f16(float* c, const uint32_t* a, const uint32_t* b) {
    asm volatile(
        "mma.sync.aligned.m16n8k16.row.col.f32.f16.f16.f32 "
        "{%0,%1,%2,%3}, {%4,%5,%6,%7}, {%8,%9}, {%0,%1,%2,%3};"
        : "+f"(c[0]), "+f"(c[1]), "+f"(c[2]), "+f"(c[3])
        : "r"(a[0]), "r"(a[1]), "r"(a[2]), "r"(a[3]), "r"(b[0]), "r"(b[1]));
}

// ======================= fp16 NT GEMM (cp.async + ldmatrix) ================
// C[m,n] = alpha * sum_k A[m,k]*B[n,k], fp16 inputs, fp32 accum.
// BM=BN=128, BK=32.  8 warps (4m x 2n), warp tile 32x64.  4-stage cp.async.
// SMEM tile: 64B rows (32 halves); 16B chunk c of row r stored at c^((r>>1)&3)
// -> conflict-free cp.async fill AND ldmatrix reads.
static constexpr int PIPE_S = 4;
static constexpr int STAGE_BYTES = 16384;               // A 8KB + B 8KB
static constexpr int SMEM_BYTES  = PIPE_S * STAGE_BYTES; // 64 KB

template<bool HALF_OUT, bool GATED>
__global__ __launch_bounds__(256, 2) void hgemm_nt(
    const __half* __restrict__ A, const __half* __restrict__ B, void* __restrict__ Cv,
    int K, int lda, int ldb, int ldc,
    long long batchA, int groupB, long long batchB, long long batchC,
    float alpha, int causal, int truncK,
    const __half* __restrict__ G, long long batchG, int ldG)
{
    int m0 = blockIdx.y * 128, n0 = blockIdx.x * 128;
    if (causal && n0 > m0) return;
    long long z = blockIdx.z;
    A += z * batchA;
    B += (z / groupB) * batchB;
    int kmax = truncK ? min(K, m0 + 128) : K;
    int nk = kmax >> 5;

    extern __shared__ char smem[];
    uint32_t sb = smem_u32(smem);
    int tid = threadIdx.x, lane = tid & 31, wid = tid >> 5;
    int wm = wid >> 1, wn = wid & 1;
    int grp = lane >> 3, l7 = lane & 7;

    auto fill = [&](int st, int kt) {
        int k0 = kt << 5;
        uint32_t base = sb + st * STAGE_BYTES;
        #pragma unroll
        for (int i = 0; i < 2; i++) {
            int id = tid + i * 256, r = id >> 2, c = id & 3;
            uint32_t dst = base + r * 64 + ((c ^ ((r >> 1) & 3)) << 4);
            CP_ASYNC16(dst, A + (long long)(m0 + r) * lda + k0 + c * 8);
        }
        #pragma unroll
        for (int i = 0; i < 2; i++) {
            int id = tid + i * 256, r = id >> 2, c = id & 3;
            uint32_t dst = base + 8192 + r * 64 + ((c ^ ((r >> 1) & 3)) << 4);
            CP_ASYNC16(dst, B + (long long)(n0 + r) * ldb + k0 + c * 8);
        }
    };

    float acc[2][8][4] = {};

    #pragma unroll
    for (int st = 0; st < PIPE_S - 1; st++) {
        if (st < nk) fill(st, st);
        CP_COMMIT();
    }

    for (int kt = 0; kt < nk; kt++) {
        CP_WAIT(PIPE_S - 2);
        __syncthreads();
        if (kt + PIPE_S - 1 < nk) fill((kt + PIPE_S - 1) & 3, kt + PIPE_S - 1);
        CP_COMMIT();

        uint32_t abase = sb + (kt & 3) * STAGE_BYTES;
        uint32_t bbase = abase + 8192;
        #pragma unroll
        for (int s = 0; s < 2; s++) {
            uint32_t af[2][4], bf[4][4];
            #pragma unroll
            for (int mt = 0; mt < 2; mt++) {
                int row = wm * 32 + mt * 16 + l7 + ((grp & 1) << 3);
                int ch  = s * 2 + (grp >> 1);
                ldm_x4(af[mt], abase + row * 64 + ((ch ^ ((row >> 1) & 3)) << 4));
            }
            #pragma unroll
            for (int nt = 0; nt < 4; nt++) {
                int row = wn * 64 + nt * 16 + l7 + ((grp >> 1) << 3);
                int ch  = s * 2 + (grp & 1);
                ldm_x4(bf[nt], bbase + row * 64 + ((ch ^ ((row >> 1) & 3)) << 4));
            }
            #pragma unroll
            for (int mt = 0; mt < 2; mt++)
                #pragma unroll
                for (int nt = 0; nt < 4; nt++) {
                    mma_f16(acc[mt][nt * 2],     af[mt], &bf[nt][0]);
                    mma_f16(acc[mt][nt * 2 + 1], af[mt], &bf[nt][2]);
                }
        }
    }

    // ---- epilogue ----
    int g8 = lane >> 2, t2 = (lane & 3) * 2;
    const __half* Gp = GATED ? (G + z * batchG) : nullptr;
    #pragma unroll
    for (int mt = 0; mt < 2; mt++) {
        #pragma unroll
        for (int nt = 0; nt < 8; nt++) {
            long long row = m0 + wm * 32 + mt * 16 + g8;
            int col = n0 + wn * 64 + nt * 8 + t2;
            float2 v0 = make_float2(acc[mt][nt][0] * alpha, acc[mt][nt][1] * alpha);
            float2 v1 = make_float2(acc[mt][nt][2] * alpha, acc[mt][nt][3] * alpha);
            if (GATED) {
                float2 q0 = __half22float2(*(const __half2*)(Gp + row * ldG + col));
                float2 q1 = __half22float2(*(const __half2*)(Gp + (row + 8) * ldG + col));
                v0.x *= 1.0f / (1.0f + expf(-q0.x));
                v0.y *= 1.0f / (1.0f + expf(-q0.y));
                v1.x *= 1.0f / (1.0f + expf(-q1.x));
                v1.y *= 1.0f / (1.0f + expf(-q1.y));
            }
            if (HALF_OUT) {
                __half* C = (__half*)Cv + z * batchC;
                *(__half2*)(C + row * ldc + col)       = __floats2half2_rn(v0.x, v0.y);
                *(__half2*)(C + (row + 8) * ldc + col) = __floats2half2_rn(v1.x, v1.y);
            } else {
                float* C = (float*)Cv + z * batchC;
                *(float2*)(C + row * ldc + col)       = v0;
                *(float2*)(C + (row + 8) * ldc + col) = v1;
            }
        }
    }
}

// ============================ elementwise kernels ==========================
__global__ __launch_bounds__(256) void f2h(const float* __restrict__ s,
                                           __half* __restrict__ d, int n)
{
    int i = (blockIdx.x * 256 + threadIdx.x) * 4;
    if (i < n) {
        float4 v = *reinterpret_cast<const float4*>(s + i);
        *reinterpret_cast<__half2*>(d + i)     = __floats2half2_rn(v.x, v.y);
        *reinterpret_cast<__half2*>(d + i + 2) = __floats2half2_rn(v.z, v.w);
    }
}

// Warp-per-row RMSNorm + RoPE on fp16 rows (fp32 math).
__global__ __launch_bounds__(256) void rmsnorm_rope_h(
    __half* __restrict__ x, const float* __restrict__ w,
    const int* __restrict__ pos, int nheads, int rowStride, int headStride)
{
    int wid = threadIdx.x >> 5, lane = threadIdx.x & 31;
    int ridx = blockIdx.x * 8 + wid;
    int t = ridx / nheads, h = ridx - t * nheads;
    __half* row = x + (size_t)t * rowStride + (size_t)h * headStride;

    uint4 raw = *reinterpret_cast<const uint4*>(row + lane * 8);
    __half2 hv[4];
    *reinterpret_cast<uint4*>(hv) = raw;
    float v[8];
    #pragma unroll
    for (int j = 0; j < 4; j++) {
        float2 f = __half22float2(hv[j]);
        v[2 * j] = f.x; v[2 * j + 1] = f.y;
    }
    float s = 0.f;
    #pragma unroll
    for (int j = 0; j < 8; j++) s += v[j] * v[j];
    #pragma unroll
    for (int o = 16; o; o >>= 1) s += __shfl_xor_sync(0xffffffffu, s, o);
    float rinv = rsqrtf(s * (1.0f / 256.0f) + 1e-6f);

    float4 w1 = *reinterpret_cast<const float4*>(w + lane * 8);
    float4 w2 = *reinterpret_cast<const float4*>(w + lane * 8 + 4);
    float y[8] = { v[0] * rinv * (1.0f + w1.x), v[1] * rinv * (1.0f + w1.y),
                   v[2] * rinv * (1.0f + w1.z), v[3] * rinv * (1.0f + w1.w),
                   v[4] * rinv * (1.0f + w2.x), v[5] * rinv * (1.0f + w2.y),
                   v[6] * rinv * (1.0f + w2.z), v[7] * rinv * (1.0f + w2.w) };

    // RoPE: dims 0..63 live in lanes 0..7; pair (d, d+32) is 4 lanes apart.
    float oth[8];
    #pragma unroll
    for (int j = 0; j < 8; j++) oth[j] = __shfl_xor_sync(0xffffffffu, y[j], 4);
    if (lane < 8) {
        float p = (float)pos[t];
        #pragma unroll
        for (int j = 0; j < 8; j++) {
            int d = lane * 8 + j;
            int fi = d & 31;
            float inv = expf(-(float)fi * (16.118095650958322f / 32.0f));
            float sn, cs;
            sincosf(p * inv, &sn, &cs);
            if (lane < 4) y[j] = y[j] * cs - oth[j] * sn;   // x1' = x1 c - x2 s
            else          y[j] = y[j] * cs + oth[j] * sn;   // x2' = x2 c + x1 s
        }
    }
    #pragma unroll
    for (int j = 0; j < 4; j++) hv[j] = __floats2half2_rn(y[2 * j], y[2 * j + 1]);
    *reinterpret_cast<uint4*>(row + lane * 8) = *reinterpret_cast<uint4*>(hv);
}

// Causal softmax: reads f32 scores, writes fp16 probs IN PLACE (first half of
// each row's storage, row stride 2*SEQ halves). Writes zeros up to the PV
// truncation bound, nothing beyond.
__global__ __launch_bounds__(256) void softmax_causal(float* __restrict__ S)
{
    int q = blockIdx.x, h = blockIdx.y;
    float* row = S + ((size_t)h * SEQ + q) * (size_t)SEQ;
    int n = q + 1;
    int nw = min(SEQ, ((q >> 7) + 1) << 7);
    int tid = threadIdx.x;

    float vals[SEQ / 256];
    float m = -3.4e38f;
    #pragma unroll
    for (int i = 0; i < SEQ / 256; i++) {
        int k = tid + i * 256;
        float v = (k < n) ? row[k] : -3.4e38f;
        vals[i] = v;
        m = fmaxf(m, v);
    }
    __shared__ float red[8];
    #pragma unroll
    for (int o = 16; o; o >>= 1) m = fmaxf(m, __shfl_xor_sync(0xffffffffu, m, o));
    if ((tid & 31) == 0) red[tid >> 5] = m;
    __syncthreads();
    if (tid < 32) {
        float x = (tid < 8) ? red[tid] : -3.4e38f;
        #pragma unroll
        for (int o = 4; o; o >>= 1) x = fmaxf(x, __shfl_xor_sync(0xffffffffu, x, o));
        if (tid == 0) red[0] = x;
    }
    __syncthreads();
    m = red[0];
    __syncthreads();

    float ssum = 0.f;
    #pragma unroll
    for (int i = 0; i < SEQ / 256; i++) {
        int k = tid + i * 256;
        float e = (k < n) ? expf(vals[i] - m) : 0.f;
        vals[i] = e;
        ssum += e;
    }
    #pragma unroll
    for (int o = 16; o; o >>= 1) ssum += __shfl_xor_sync(0xffffffffu, ssum, o);
    if ((tid & 31) == 0) red[tid >> 5] = ssum;
    __syncthreads();
    if (tid < 32) {
        float x = (tid < 8) ? red[tid] : 0.f;
        #pragma unroll
        for (int o = 4; o; o >>= 1) x += __shfl_xor_sync(0xffffffffu, x, o);
        if (tid == 0) red[0] = x;
    }
    __syncthreads();
    float inv = 1.0f / red[0];
    __half* p = reinterpret_cast<__half*>(row);
    #pragma unroll
    for (int i = 0; i < SEQ / 256; i++) {
        int k = tid + i * 256;
        if (k < nw) p[k] = __float2half(vals[i] * inv);
    }
}

// ============================ host launch ==================================
extern "C" void kernel_launch(void* const* d_in, const int* in_sizes, int n_in,
                              void* d_out, int out_size)
{
    const int*   positions = (const int*)d_in[0];
    const float* hs  = (const float*)d_in[1];
    const float* wq  = (const float*)d_in[2];
    const float* wk  = (const float*)d_in[3];
    const float* wv  = (const float*)d_in[4];
    const float* wo  = (const float*)d_in[5];
    const float* qnw = (const float*)d_in[6];
    const float* knw = (const float*)d_in[7];
    float* out = (float*)d_out;

    __half *hhs, *hwq, *hwk, *hwv, *hwo, *hq, *hk, *hvt, *ho;
    float* sbuf;
    cudaGetSymbolAddress((void**)&hhs, g_hs_h);
    cudaGetSymbolAddress((void**)&hwq, g_wq_h);
    cudaGetSymbolAddress((void**)&hwk, g_wk_h);
    cudaGetSymbolAddress((void**)&hwv, g_wv_h);
    cudaGetSymbolAddress((void**)&hwo, g_wo_h);
    cudaGetSymbolAddress((void**)&hq,  g_qout_h);
    cudaGetSymbolAddress((void**)&hk,  g_kbuf_h);
    cudaGetSymbolAddress((void**)&hvt, g_vt_h);
    cudaGetSymbolAddress((void**)&ho,  g_obuf_h);
    cudaGetSymbolAddress((void**)&sbuf, g_sbuf);

    cudaFuncSetAttribute(hgemm_nt<true,  false>,
                         cudaFuncAttributeMaxDynamicSharedMemorySize, SMEM_BYTES);
    cudaFuncSetAttribute(hgemm_nt<true,  true>,
                         cudaFuncAttributeMaxDynamicSharedMemorySize, SMEM_BYTES);
    cudaFuncSetAttribute(hgemm_nt<false, false>,
                         cudaFuncAttributeMaxDynamicSharedMemorySize, SMEM_BYTES);

    dim3 blk(256);

    // 0) fp32 -> fp16 conversions
    f2h<<<SEQ * HIDDEN / 1024, 256>>>(hs, hhs, SEQ * HIDDEN);
    f2h<<<QROW * HIDDEN / 1024, 256>>>(wq, hwq, QROW * HIDDEN);
    f2h<<<KROW * HIDDEN / 1024, 256>>>(wk, hwk, KROW * HIDDEN);
    f2h<<<KROW * HIDDEN / 1024, 256>>>(wv, hwv, KROW * HIDDEN);
    f2h<<<HIDDEN * ODIM / 1024, 256>>>(wo, hwo, HIDDEN * ODIM);

    // 1) Q projection: hq = hs @ wq^T          [2048 x 8192] fp16
    hgemm_nt<true, false><<<dim3(QROW / 128, SEQ / 128, 1), blk, SMEM_BYTES>>>(
        hhs, hwq, hq, HIDDEN, HIDDEN, HIDDEN, QROW, 0, 1, 0, 0, 1.0f, 0, 0,
        nullptr, 0, 0);
    // 2) K projection: hk = hs @ wk^T          [2048 x 512] fp16
    hgemm_nt<true, false><<<dim3(KROW / 128, SEQ / 128, 1), blk, SMEM_BYTES>>>(
        hhs, hwk, hk, HIDDEN, HIDDEN, HIDDEN, KROW, 0, 1, 0, 0, 1.0f, 0, 0,
        nullptr, 0, 0);
    // 3) V^T: hvt = wv @ hs^T                  [512 x 2048] fp16
    hgemm_nt<true, false><<<dim3(SEQ / 128, KROW / 128, 1), blk, SMEM_BYTES>>>(
        hwv, hhs, hvt, HIDDEN, HIDDEN, HIDDEN, SEQ, 0, 1, 0, 0, 1.0f, 0, 0,
        nullptr, 0, 0);

    // 4) RMSNorm + RoPE in place (fp16)
    rmsnorm_rope_h<<<SEQ * NHEAD / 8, 256>>>(hq, qnw, positions, NHEAD, QROW, 2 * HD);
    rmsnorm_rope_h<<<SEQ * NKV / 8, 256>>>(hk, knw, positions, NKV, KROW, HD);

    // 5) Scores (f32 out): S[h][q][k] = scale * q.k   (causal tile skip)
    hgemm_nt<false, false><<<dim3(SEQ / 128, SEQ / 128, NHEAD), blk, SMEM_BYTES>>>(
        hq, hk, sbuf, HD, QROW, KROW, SEQ,
        /*batchA=*/2 * HD, /*groupB=*/NHEAD / NKV, /*batchB=*/HD,
        /*batchC=*/(long long)SEQ * SEQ, ATTN_SCALE, /*causal=*/1, 0,
        nullptr, 0, 0);

    // 6) Softmax: f32 scores -> fp16 probs in place (row stride 2*SEQ halves)
    softmax_causal<<<dim3(SEQ, NHEAD), 256>>>(sbuf);

    // 7) O = P @ V via NT with V^T, K truncated, fused sigmoid gate (fp16 out)
    hgemm_nt<true, true><<<dim3(HD / 128, SEQ / 128, NHEAD), blk, SMEM_BYTES>>>(
        (const __half*)sbuf, hvt, ho, SEQ, 2 * SEQ, SEQ, ODIM,
        /*batchA=*/(long long)SEQ * 2 * SEQ, /*groupB=*/NHEAD / NKV,
        /*batchB=*/(long long)HD * SEQ, /*batchC=*/HD, 1.0f, 0, /*truncK=*/1,
        /*G=*/hq + HD, /*batchG=*/2 * HD, /*ldG=*/QROW);

    // 8) Output projection (f32 out): out = obuf @ wo^T
    hgemm_nt<false, false><<<dim3(HIDDEN / 128, SEQ / 128, 1), blk, SMEM_BYTES>>>(
        ho, hwo, out, ODIM, ODIM, ODIM, HIDDEN, 0, 1, 0, 0, 1.0f, 0, 0,
        nullptr, 0, 0);
}

// round 7
// speedup vs baseline: 3.1584x; 1.2259x over previous
#include <cuda_runtime.h>
#include <cuda_fp16.h>
#include <math.h>
#include <stdint.h>

static constexpr int SEQ    = 2048;
static constexpr int HIDDEN = 2048;
static constexpr int NHEAD  = 16;
static constexpr int NKV    = 2;
static constexpr int HD     = 256;
static constexpr int QROW   = NHEAD * HD * 2;   // 8192
static constexpr int KROW   = NKV * HD;         // 512
static constexpr int ODIM   = NHEAD * HD;       // 4096
static constexpr float ATTN_SCALE = 0.0625f;
static constexpr float MASKV = -1e30f;

// ---- scratch (static device memory; no allocations allowed) ----
__device__ __half g_hs_h  [(size_t)SEQ * HIDDEN];
__device__ __half g_wq_h  [(size_t)QROW * HIDDEN];
__device__ __half g_wk_h  [(size_t)KROW * HIDDEN];
__device__ __half g_wv_h  [(size_t)KROW * HIDDEN];
__device__ __half g_wo_h  [(size_t)HIDDEN * ODIM];
__device__ __half g_qout_h[(size_t)SEQ * QROW];
__device__ __half g_kbuf_h[(size_t)SEQ * KROW];
__device__ __half g_vt_h  [(size_t)KROW * SEQ];
__device__ __half g_obuf_h[(size_t)SEQ * ODIM];

// ============================ asm helpers ==================================
__device__ __forceinline__ uint32_t smem_u32(const void* p) {
    uint32_t a;
    asm("{ .reg .u64 t; cvta.to.shared.u64 t, %1; cvt.u32.u64 %0, t; }" : "=r"(a) : "l"(p));
    return a;
}
#define CP_ASYNC16(dst, src) \
    asm volatile("cp.async.cg.shared.global [%0], [%1], 16;" :: "r"(dst), "l"(src))
#define CP_COMMIT() asm volatile("cp.async.commit_group;")
#define CP_WAIT(n)  asm volatile("cp.async.wait_group %0;" :: "n"(n))

__device__ __forceinline__ void ldm_x4(uint32_t* r, uint32_t addr) {
    asm volatile("ldmatrix.sync.aligned.m8n8.x4.shared.b16 {%0,%1,%2,%3}, [%4];"
                 : "=r"(r[0]), "=r"(r[1]), "=r"(r[2]), "=r"(r[3]) : "r"(addr));
}
__device__ __forceinline__ void mma_f16(float* c, const uint32_t* a, const uint32_t* b) {
    asm volatile(
        "mma.sync.aligned.m16n8k16.row.col.f32.f16.f16.f32 "
        "{%0,%1,%2,%3}, {%4,%5,%6,%7}, {%8,%9}, {%0,%1,%2,%3};"
        : "+f"(c[0]), "+f"(c[1]), "+f"(c[2]), "+f"(c[3])
        : "r"(a[0]), "r"(a[1]), "r"(a[2]), "r"(a[3]), "r"(b[0]), "r"(b[1]));
}
__device__ __forceinline__ uint32_t h2u(__half2 v) {
    return *reinterpret_cast<uint32_t*>(&v);
}

// ======================= fp16 NT GEMM (cp.async + ldmatrix) ================
// C[m,n] = sum_k A[m,k]*B[n,k], fp16 in, fp32 accum. 128x128x32 tiles,
// 8 warps (4m x 2n), 4-stage cp.async, swizzled 64B rows.
static constexpr int PIPE_S = 4;
static constexpr int STAGE_BYTES = 16384;
static constexpr int SMEM_BYTES  = PIPE_S * STAGE_BYTES;   // 64 KB

template<bool HALF_OUT>
__device__ __forceinline__ void hgemm_body(
    const __half* __restrict__ A, const __half* __restrict__ B, void* __restrict__ Cv,
    int m0, int n0, int K, int lda, int ldb, int ldc)
{
    int nk = K >> 5;
    extern __shared__ char smem[];
    uint32_t sb = smem_u32(smem);
    int tid = threadIdx.x, lane = tid & 31, wid = tid >> 5;
    int wm = wid >> 1, wn = wid & 1;
    int grp = lane >> 3, l7 = lane & 7;

    auto fill = [&](int st, int kt) {
        int k0 = kt << 5;
        uint32_t base = sb + st * STAGE_BYTES;
        #pragma unroll
        for (int i = 0; i < 2; i++) {
            int id = tid + i * 256, r = id >> 2, c = id & 3;
            CP_ASYNC16(base + r * 64 + ((c ^ ((r >> 1) & 3)) << 4),
                       A + (long long)(m0 + r) * lda + k0 + c * 8);
        }
        #pragma unroll
        for (int i = 0; i < 2; i++) {
            int id = tid + i * 256, r = id >> 2, c = id & 3;
            CP_ASYNC16(base + 8192 + r * 64 + ((c ^ ((r >> 1) & 3)) << 4),
                       B + (long long)(n0 + r) * ldb + k0 + c * 8);
        }
    };

    float acc[2][8][4] = {};

    #pragma unroll
    for (int st = 0; st < PIPE_S - 1; st++) {
        if (st < nk) fill(st, st);
        CP_COMMIT();
    }

    for (int kt = 0; kt < nk; kt++) {
        CP_WAIT(PIPE_S - 2);
        __syncthreads();
        if (kt + PIPE_S - 1 < nk) fill((kt + PIPE_S - 1) & 3, kt + PIPE_S - 1);
        CP_COMMIT();

        uint32_t abase = sb + (kt & 3) * STAGE_BYTES;
        uint32_t bbase = abase + 8192;
        #pragma unroll
        for (int s = 0; s < 2; s++) {
            uint32_t af[2][4], bf[4][4];
            #pragma unroll
            for (int mt = 0; mt < 2; mt++) {
                int row = wm * 32 + mt * 16 + l7 + ((grp & 1) << 3);
                int ch  = s * 2 + (grp >> 1);
                ldm_x4(af[mt], abase + row * 64 + ((ch ^ ((row >> 1) & 3)) << 4));
            }
            #pragma unroll
            for (int nt = 0; nt < 4; nt++) {
                int row = wn * 64 + nt * 16 + l7 + ((grp >> 1) << 3);
                int ch  = s * 2 + (grp & 1);
                ldm_x4(bf[nt], bbase + row * 64 + ((ch ^ ((row >> 1) & 3)) << 4));
            }
            #pragma unroll
            for (int mt = 0; mt < 2; mt++)
                #pragma unroll
                for (int nt = 0; nt < 4; nt++) {
                    mma_f16(acc[mt][nt * 2],     af[mt], &bf[nt][0]);
                    mma_f16(acc[mt][nt * 2 + 1], af[mt], &bf[nt][2]);
                }
        }
    }

    int g8 = lane >> 2, t2 = (lane & 3) * 2;
    #pragma unroll
    for (int mt = 0; mt < 2; mt++) {
        #pragma unroll
        for (int nt = 0; nt < 8; nt++) {
            long long row = m0 + wm * 32 + mt * 16 + g8;
            int col = n0 + wn * 64 + nt * 8 + t2;
            if (HALF_OUT) {
                __half* C = (__half*)Cv;
                *(__half2*)(C + row * ldc + col) =
                    __floats2half2_rn(acc[mt][nt][0], acc[mt][nt][1]);
                *(__half2*)(C + (row + 8) * ldc + col) =
                    __floats2half2_rn(acc[mt][nt][2], acc[mt][nt][3]);
            } else {
                float* C = (float*)Cv;
                *(float2*)(C + row * ldc + col) =
                    make_float2(acc[mt][nt][0], acc[mt][nt][1]);
                *(float2*)(C + (row + 8) * ldc + col) =
                    make_float2(acc[mt][nt][2], acc[mt][nt][3]);
            }
        }
    }
}

template<bool HALF_OUT>
__global__ __launch_bounds__(256, 2) void hgemm_nt(
    const __half* __restrict__ A, const __half* __restrict__ B, void* __restrict__ Cv,
    int K, int lda, int ldb, int ldc)
{
    hgemm_body<HALF_OUT>(A, B, Cv, blockIdx.y * 128, blockIdx.x * 128, K, lda, ldb, ldc);
}

// Combined K-projection + V^T-projection (each alone only fills 64 CTAs).
__global__ __launch_bounds__(256, 2) void hgemm_kv(
    const __half* __restrict__ hs, const __half* __restrict__ wk,
    const __half* __restrict__ wv, __half* __restrict__ kout,
    __half* __restrict__ vtout)
{
    int b = blockIdx.x;
    if (b < 64) {       // kout = hs @ wk^T   [2048 x 512]
        hgemm_body<true>(hs, wk, kout, (b >> 2) << 7, (b & 3) << 7,
                         HIDDEN, HIDDEN, HIDDEN, KROW);
    } else {            // vtout = wv @ hs^T  [512 x 2048]
        int b2 = b - 64;
        hgemm_body<true>(wv, hs, vtout, (b2 >> 4) << 7, (b2 & 15) << 7,
                         HIDDEN, HIDDEN, HIDDEN, SEQ);
    }
}

// ======================= fused flash attention =============================
// CTA: 128 q-rows x 1 head. 8 warps; warp = 16 q-rows x full 256 d.
// Iterates k in tiles of 64 (double-buffered cp.async). Online softmax fp32,
// P in fp16 (S-accum fragments reused as A operand). Gated epilogue.
// SMEM: Q 64KB + 2 stages x (K 32KB + Vt 32KB) = 192KB -> 1 CTA/SM.
static constexpr int FQ_BYTES = 128 * 512;
static constexpr int FK_BYTES = 64 * 512;
static constexpr int FSTAGE   = FK_BYTES + 256 * 128;      // 65536
static constexpr int FSMEM    = FQ_BYTES + 2 * FSTAGE;     // 196608

__global__ __launch_bounds__(256, 1) void flash_attn(
    const __half* __restrict__ Qh, const __half* __restrict__ Kh,
    const __half* __restrict__ Vth, __half* __restrict__ O)
{
    int bx = blockIdx.x;
    int qt = 15 - (bx >> 4);          // heavy q-tiles first
    int h  = bx & 15;
    int q0 = qt << 7;
    int kv = h >> 3;
    int niter = (qt + 1) << 1;

    extern __shared__ char smem[];
    uint32_t sq = smem_u32(smem);

    int tid = threadIdx.x, lane = tid & 31, wid = tid >> 5;
    int grp = lane >> 3, l7 = lane & 7;
    int g8 = lane >> 2, t2 = (lane & 3) << 1;

    // Q tile: 128 rows x 512B, chunk c of row r at (c ^ (r&7))
    #pragma unroll
    for (int i = 0; i < 16; i++) {
        int id = tid + (i << 8);
        int r = id >> 5, c = id & 31;
        CP_ASYNC16(sq + r * 512 + ((c ^ (r & 7)) << 4),
                   Qh + (size_t)(q0 + r) * QROW + h * 512 + c * 8);
    }
    auto fillKV = [&](int it, int st) {
        int k0 = it << 6;
        uint32_t kb = sq + FQ_BYTES + st * FSTAGE;
        uint32_t vb = kb + FK_BYTES;
        #pragma unroll
        for (int i = 0; i < 8; i++) {
            int id = tid + (i << 8);
            int r = id >> 5, c = id & 31;
            CP_ASYNC16(kb + r * 512 + ((c ^ (r & 7)) << 4),
                       Kh + (size_t)(k0 + r) * KROW + kv * 256 + c * 8);
        }
        #pragma unroll
        for (int i = 0; i < 8; i++) {
            int id = tid + (i << 8);
            int d = id >> 3, c = id & 7;
            CP_ASYNC16(vb + d * 128 + ((c ^ (d & 7)) << 4),
                       Vth + (size_t)(kv * 256 + d) * SEQ + k0 + c * 8);
        }
    };
    fillKV(0, 0);
    CP_COMMIT();
    if (niter > 1) { fillKV(1, 1); CP_COMMIT(); }

    float m0 = MASKV, m1 = MASKV, l0 = 0.f, l1 = 0.f;
    float accO[32][4] = {};
    int qrow0 = q0 + wid * 16 + g8;

    for (int it = 0; it < niter; it++) {
        int k0 = it << 6;
        if (it + 1 < niter) { CP_WAIT(1); } else { CP_WAIT(0); }
        __syncthreads();

        uint32_t kb = sq + FQ_BYTES + (it & 1) * FSTAGE;
        uint32_t vb = kb + FK_BYTES;

        // ---- S = Q K^T (warp: 16q x 64k) ----
        float accS[8][4] = {};
        #pragma unroll
        for (int s = 0; s < 16; s++) {
            uint32_t af[4];
            int qr = wid * 16 + l7 + ((grp & 1) << 3);
            int ch = s * 2 + (grp >> 1);
            ldm_x4(af, sq + qr * 512 + ((ch ^ (qr & 7)) << 4));
            #pragma unroll
            for (int np = 0; np < 4; np++) {
                uint32_t bf[4];
                int kr = np * 16 + l7 + ((grp >> 1) << 3);
                int c2 = s * 2 + (grp & 1);
                ldm_x4(bf, kb + kr * 512 + ((c2 ^ (kr & 7)) << 4));
                mma_f16(accS[np * 2],     af, &bf[0]);
                mma_f16(accS[np * 2 + 1], af, &bf[2]);
            }
        }
        #pragma unroll
        for (int nt = 0; nt < 8; nt++)
            #pragma unroll
            for (int q = 0; q < 4; q++) accS[nt][q] *= ATTN_SCALE;

        if (k0 + 63 > q0 + wid * 16) {       // causal mask (diagonal tiles)
            #pragma unroll
            for (int nt = 0; nt < 8; nt++) {
                int c0 = k0 + nt * 8 + t2;
                if (c0 > qrow0)         accS[nt][0] = MASKV;
                if (c0 + 1 > qrow0)     accS[nt][1] = MASKV;
                if (c0 > qrow0 + 8)     accS[nt][2] = MASKV;
                if (c0 + 1 > qrow0 + 8) accS[nt][3] = MASKV;
            }
        }

        // ---- online softmax (rows g8 / g8+8; 4 lanes share a row) ----
        float mx0 = MASKV, mx1 = MASKV;
        #pragma unroll
        for (int nt = 0; nt < 8; nt++) {
            mx0 = fmaxf(mx0, fmaxf(accS[nt][0], accS[nt][1]));
            mx1 = fmaxf(mx1, fmaxf(accS[nt][2], accS[nt][3]));
        }
        mx0 = fmaxf(mx0, __shfl_xor_sync(0xffffffffu, mx0, 1));
        mx0 = fmaxf(mx0, __shfl_xor_sync(0xffffffffu, mx0, 2));
        mx1 = fmaxf(mx1, __shfl_xor_sync(0xffffffffu, mx1, 1));
        mx1 = fmaxf(mx1, __shfl_xor_sync(0xffffffffu, mx1, 2));

        float mn0 = fmaxf(m0, mx0), mn1 = fmaxf(m1, mx1);
        float a0 = __expf(m0 - mn0), a1 = __expf(m1 - mn1);
        m0 = mn0; m1 = mn1;
        float s0 = 0.f, s1 = 0.f;
        #pragma unroll
        for (int nt = 0; nt < 8; nt++) {
            accS[nt][0] = __expf(accS[nt][0] - mn0); s0 += accS[nt][0];
            accS[nt][1] = __expf(accS[nt][1] - mn0); s0 += accS[nt][1];
            accS[nt][2] = __expf(accS[nt][2] - mn1); s1 += accS[nt][2];
            accS[nt][3] = __expf(accS[nt][3] - mn1); s1 += accS[nt][3];
        }
        s0 += __shfl_xor_sync(0xffffffffu, s0, 1);
        s0 += __shfl_xor_sync(0xffffffffu, s0, 2);
        s1 += __shfl_xor_sync(0xffffffffu, s1, 1);
        s1 += __shfl_xor_sync(0xffffffffu, s1, 2);
        l0 = l0 * a0 + s0;
        l1 = l1 * a1 + s1;
        #pragma unroll
        for (int nt = 0; nt < 32; nt++) {
            accO[nt][0] *= a0; accO[nt][1] *= a0;
            accO[nt][2] *= a1; accO[nt][3] *= a1;
        }

        // ---- P fragments (S accum layout == A operand layout) ----
        uint32_t pf[4][4];
        #pragma unroll
        for (int kc = 0; kc < 4; kc++) {
            pf[kc][0] = h2u(__floats2half2_rn(accS[2 * kc][0],     accS[2 * kc][1]));
            pf[kc][1] = h2u(__floats2half2_rn(accS[2 * kc][2],     accS[2 * kc][3]));
            pf[kc][2] = h2u(__floats2half2_rn(accS[2 * kc + 1][0], accS[2 * kc + 1][1]));
            pf[kc][3] = h2u(__floats2half2_rn(accS[2 * kc + 1][2], accS[2 * kc + 1][3]));
        }

        // ---- O += P V  (warp: 16q x 256d) ----
        #pragma unroll
        for (int np = 0; np < 16; np++) {
            #pragma unroll
            for (int kc = 0; kc < 4; kc++) {
                uint32_t bf[4];
                int dr = np * 16 + l7 + ((grp >> 1) << 3);
                int ch = kc * 2 + (grp & 1);
                ldm_x4(bf, vb + dr * 128 + ((ch ^ (dr & 7)) << 4));
                mma_f16(accO[np * 2],     pf[kc], &bf[0]);
                mma_f16(accO[np * 2 + 1], pf[kc], &bf[2]);
            }
        }

        __syncthreads();
        if (it + 2 < niter) { fillKV(it + 2, it & 1); CP_COMMIT(); }
    }

    // ---- epilogue: 1/l, sigmoid gate, fp16 store ----
    float r0 = 1.f / l0, r1 = 1.f / l1;
    int trow0 = qrow0, trow1 = qrow0 + 8;
    const __half* G0 = Qh + (size_t)trow0 * QROW + h * 512 + 256;
    const __half* G1 = Qh + (size_t)trow1 * QROW + h * 512 + 256;
    __half* O0 = O + (size_t)trow0 * ODIM + h * 256;
    __half* O1 = O + (size_t)trow1 * ODIM + h * 256;
    #pragma unroll
    for (int nt = 0; nt < 32; nt++) {
        int d = nt * 8 + t2;
        float2 ga = __half22float2(*(const __half2*)(G0 + d));
        float2 gb = __half22float2(*(const __half2*)(G1 + d));
        float vx = accO[nt][0] * r0 / (1.f + __expf(-ga.x));
        float vy = accO[nt][1] * r0 / (1.f + __expf(-ga.y));
        float wx = accO[nt][2] * r1 / (1.f + __expf(-gb.x));
        float wy = accO[nt][3] * r1 / (1.f + __expf(-gb.y));
        *(__half2*)(O0 + d) = __floats2half2_rn(vx, vy);
        *(__half2*)(O1 + d) = __floats2half2_rn(wx, wy);
    }
}

// ============================ elementwise kernels ==========================
__global__ __launch_bounds__(256) void f2h(const float* __restrict__ s,
                                           __half* __restrict__ d, int n)
{
    int i = (blockIdx.x * 256 + threadIdx.x) * 4;
    if (i < n) {
        float4 v = *reinterpret_cast<const float4*>(s + i);
        *reinterpret_cast<__half2*>(d + i)     = __floats2half2_rn(v.x, v.y);
        *reinterpret_cast<__half2*>(d + i + 2) = __floats2half2_rn(v.z, v.w);
    }
}

// Warp-per-row RMSNorm + RoPE on fp16 rows; q-rows and k-rows in one launch.
__global__ __launch_bounds__(256) void rmsnorm_rope_h(
    __half* __restrict__ xq, const float* __restrict__ wq,
    __half* __restrict__ xk, const float* __restrict__ wk,
    const int* __restrict__ pos)
{
    int widx = threadIdx.x >> 5, lane = threadIdx.x & 31;
    int ridx = blockIdx.x * 8 + widx;
    __half* row;
    const float* w;
    int t;
    if (ridx < SEQ * NHEAD) {
        t = ridx >> 4;
        int h = ridx & 15;
        row = xq + (size_t)t * QROW + (size_t)h * 512;
        w = wq;
    } else {
        int r2 = ridx - SEQ * NHEAD;
        t = r2 >> 1;
        int h = r2 & 1;
        row = xk + (size_t)t * KROW + (size_t)h * HD;
        w = wk;
    }

    uint4 raw = *reinterpret_cast<const uint4*>(row + lane * 8);
    __half2 hv[4];
    *reinterpret_cast<uint4*>(hv) = raw;
    float v[8];
    #pragma unroll
    for (int j = 0; j < 4; j++) {
        float2 f = __half22float2(hv[j]);
        v[2 * j] = f.x; v[2 * j + 1] = f.y;
    }
    float s = 0.f;
    #pragma unroll
    for (int j = 0; j < 8; j++) s += v[j] * v[j];
    #pragma unroll
    for (int o = 16; o; o >>= 1) s += __shfl_xor_sync(0xffffffffu, s, o);
    float rinv = rsqrtf(s * (1.0f / 256.0f) + 1e-6f);

    float4 w1 = *reinterpret_cast<const float4*>(w + lane * 8);
    float4 w2 = *reinterpret_cast<const float4*>(w + lane * 8 + 4);
    float y[8] = { v[0] * rinv * (1.0f + w1.x), v[1] * rinv * (1.0f + w1.y),
                   v[2] * rinv * (1.0f + w1.z), v[3] * rinv * (1.0f + w1.w),
                   v[4] * rinv * (1.0f + w2.x), v[5] * rinv * (1.0f + w2.y),
                   v[6] * rinv * (1.0f + w2.z), v[7] * rinv * (1.0f + w2.w) };

    float oth[8];
    #pragma unroll
    for (int j = 0; j < 8; j++) oth[j] = __shfl_xor_sync(0xffffffffu, y[j], 4);
    if (lane < 8) {
        float p = (float)pos[t];
        #pragma unroll
        for (int j = 0; j < 8; j++) {
            int d = lane * 8 + j;
            int fi = d & 31;
            float inv = expf(-(float)fi * (16.118095650958322f / 32.0f));
            float sn, cs;
            sincosf(p * inv, &sn, &cs);
            if (lane < 4) y[j] = y[j] * cs - oth[j] * sn;
            else          y[j] = y[j] * cs + oth[j] * sn;
        }
    }
    #pragma unroll
    for (int j = 0; j < 4; j++) hv[j] = __floats2half2_rn(y[2 * j], y[2 * j + 1]);
    *reinterpret_cast<uint4*>(row + lane * 8) = *reinterpret_cast<uint4*>(hv);
}

// ============================ host launch ==================================
extern "C" void kernel_launch(void* const* d_in, const int* in_sizes, int n_in,
                              void* d_out, int out_size)
{
    const int*   positions = (const int*)d_in[0];
    const float* hs  = (const float*)d_in[1];
    const float* wq  = (const float*)d_in[2];
    const float* wk  = (const float*)d_in[3];
    const float* wv  = (const float*)d_in[4];
    const float* wo  = (const float*)d_in[5];
    const float* qnw = (const float*)d_in[6];
    const float* knw = (const float*)d_in[7];
    float* out = (float*)d_out;

    __half *hhs, *hwq, *hwk, *hwv, *hwo, *hq, *hk, *hvt, *ho;
    cudaGetSymbolAddress((void**)&hhs, g_hs_h);
    cudaGetSymbolAddress((void**)&hwq, g_wq_h);
    cudaGetSymbolAddress((void**)&hwk, g_wk_h);
    cudaGetSymbolAddress((void**)&hwv, g_wv_h);
    cudaGetSymbolAddress((void**)&hwo, g_wo_h);
    cudaGetSymbolAddress((void**)&hq,  g_qout_h);
    cudaGetSymbolAddress((void**)&hk,  g_kbuf_h);
    cudaGetSymbolAddress((void**)&hvt, g_vt_h);
    cudaGetSymbolAddress((void**)&ho,  g_obuf_h);

    cudaFuncSetAttribute(hgemm_nt<true>,
                         cudaFuncAttributeMaxDynamicSharedMemorySize, SMEM_BYTES);
    cudaFuncSetAttribute(hgemm_nt<false>,
                         cudaFuncAttributeMaxDynamicSharedMemorySize, SMEM_BYTES);
    cudaFuncSetAttribute(hgemm_kv,
                         cudaFuncAttributeMaxDynamicSharedMemorySize, SMEM_BYTES);
    cudaFuncSetAttribute(flash_attn,
                         cudaFuncAttributeMaxDynamicSharedMemorySize, FSMEM);

    dim3 blk(256);

    // 0) fp32 -> fp16
    f2h<<<SEQ * HIDDEN / 1024, 256>>>(hs, hhs, SEQ * HIDDEN);
    f2h<<<QROW * HIDDEN / 1024, 256>>>(wq, hwq, QROW * HIDDEN);
    f2h<<<KROW * HIDDEN / 1024, 256>>>(wk, hwk, KROW * HIDDEN);
    f2h<<<KROW * HIDDEN / 1024, 256>>>(wv, hwv, KROW * HIDDEN);
    f2h<<<HIDDEN * ODIM / 1024, 256>>>(wo, hwo, HIDDEN * ODIM);

    // 1) Q projection: hq = hs @ wq^T   [2048 x 8192]
    hgemm_nt<true><<<dim3(QROW / 128, SEQ / 128, 1), blk, SMEM_BYTES>>>(
        hhs, hwq, hq, HIDDEN, HIDDEN, HIDDEN, QROW);
    // 2+3) K projection + V^T projection in one launch (128 CTAs)
    hgemm_kv<<<128, blk, SMEM_BYTES>>>(hhs, hwk, hwv, hk, hvt);

    // 4) RMSNorm + RoPE (q rows + k rows in one launch)
    rmsnorm_rope_h<<<(SEQ * NHEAD + SEQ * NKV) / 8, 256>>>(
        hq, qnw, hk, knw, positions);

    // 5) Fused flash attention (scores + softmax + PV + gate)
    flash_attn<<<256, blk, FSMEM>>>(hq, hk, hvt, ho);

    // 6) Output projection (f32 out): out = ho @ wo^T
    hgemm_nt<false><<<dim3(HIDDEN / 128, SEQ / 128, 1), blk, SMEM_BYTES>>>(
        ho, hwo, out, ODIM, ODIM, ODIM, HIDDEN);
}

// round 9
// speedup vs baseline: 3.2729x; 1.0363x over previous
#include <cuda_runtime.h>
#include <cuda_fp16.h>
#include <math.h>
#include <stdint.h>

static constexpr int SEQ    = 2048;
static constexpr int HIDDEN = 2048;
static constexpr int NHEAD  = 16;
static constexpr int NKV    = 2;
static constexpr int HD     = 256;
static constexpr int QROW   = NHEAD * HD * 2;   // 8192
static constexpr int KROW   = NKV * HD;         // 512
static constexpr int ODIM   = NHEAD * HD;       // 4096
static constexpr float ATTN_SCALE = 0.0625f;
static constexpr float MASKV = -1e30f;

// ---- scratch (static device memory; no allocations allowed) ----
__device__ __half g_hs_h  [(size_t)SEQ * HIDDEN];
__device__ __half g_wq_h  [(size_t)QROW * HIDDEN];
__device__ __half g_wk_h  [(size_t)KROW * HIDDEN];
__device__ __half g_wv_h  [(size_t)KROW * HIDDEN];
__device__ __half g_wo_h  [(size_t)HIDDEN * ODIM];
__device__ __half g_qout_h[(size_t)SEQ * QROW];
__device__ __half g_kbuf_h[(size_t)SEQ * KROW];
__device__ __half g_vt_h  [(size_t)KROW * SEQ];
__device__ __half g_obuf_h[(size_t)SEQ * ODIM];

// ============================ asm helpers ==================================
__device__ __forceinline__ uint32_t smem_u32(const void* p) {
    uint32_t a;
    asm("{ .reg .u64 t; cvta.to.shared.u64 t, %1; cvt.u32.u64 %0, t; }" : "=r"(a) : "l"(p));
    return a;
}
#define CP_ASYNC16(dst, src) \
    asm volatile("cp.async.cg.shared.global [%0], [%1], 16;" :: "r"(dst), "l"(src))
#define CP_COMMIT() asm volatile("cp.async.commit_group;")
#define CP_WAIT(n)  asm volatile("cp.async.wait_group %0;" :: "n"(n))

__device__ __forceinline__ void ldm_x4(uint32_t* r, uint32_t addr) {
    asm volatile("ldmatrix.sync.aligned.m8n8.x4.shared.b16 {%0,%1,%2,%3}, [%4];"
                 : "=r"(r[0]), "=r"(r[1]), "=r"(r[2]), "=r"(r[3]) : "r"(addr));
}
__device__ __forceinline__ void mma_f16(float* c, const uint32_t* a, const uint32_t* b) {
    asm volatile(
        "mma.sync.aligned.m16n8k16.row.col.f32.f16.f16.f32 "
        "{%0,%1,%2,%3}, {%4,%5,%6,%7}, {%8,%9}, {%0,%1,%2,%3};"
        : "+f"(c[0]), "+f"(c[1]), "+f"(c[2]), "+f"(c[3])
        : "r"(a[0]), "r"(a[1]), "r"(a[2]), "r"(a[3]), "r"(b[0]), "r"(b[1]));
}
__device__ __forceinline__ uint32_t h2u(__half2 v) {
    return *reinterpret_cast<uint32_t*>(&v);
}

// ======================= fp16 NT GEMM (cp.async + ldmatrix) ================
static constexpr int PIPE_S = 4;
static constexpr int STAGE_BYTES = 16384;
static constexpr int SMEM_BYTES  = PIPE_S * STAGE_BYTES;   // 64 KB

template<bool HALF_OUT>
__device__ __forceinline__ void hgemm_body(
    const __half* __restrict__ A, const __half* __restrict__ B, void* __restrict__ Cv,
    int m0, int n0, int K, int lda, int ldb, int ldc)
{
    int nk = K >> 5;
    extern __shared__ char smem[];
    uint32_t sb = smem_u32(smem);
    int tid = threadIdx.x, lane = tid & 31, wid = tid >> 5;
    int wm = wid >> 1, wn = wid & 1;
    int grp = lane >> 3, l7 = lane & 7;

    auto fill = [&](int st, int kt) {
        int k0 = kt << 5;
        uint32_t base = sb + st * STAGE_BYTES;
        #pragma unroll
        for (int i = 0; i < 2; i++) {
            int id = tid + i * 256, r = id >> 2, c = id & 3;
            CP_ASYNC16(base + r * 64 + ((c ^ ((r >> 1) & 3)) << 4),
                       A + (long long)(m0 + r) * lda + k0 + c * 8);
        }
        #pragma unroll
        for (int i = 0; i < 2; i++) {
            int id = tid + i * 256, r = id >> 2, c = id & 3;
            CP_ASYNC16(base + 8192 + r * 64 + ((c ^ ((r >> 1) & 3)) << 4),
                       B + (long long)(n0 + r) * ldb + k0 + c * 8);
        }
    };

    float acc[2][8][4] = {};

    #pragma unroll
    for (int st = 0; st < PIPE_S - 1; st++) {
        if (st < nk) fill(st, st);
        CP_COMMIT();
    }

    for (int kt = 0; kt < nk; kt++) {
        CP_WAIT(PIPE_S - 2);
        __syncthreads();
        if (kt + PIPE_S - 1 < nk) fill((kt + PIPE_S - 1) & 3, kt + PIPE_S - 1);
        CP_COMMIT();

        uint32_t abase = sb + (kt & 3) * STAGE_BYTES;
        uint32_t bbase = abase + 8192;
        #pragma unroll
        for (int s = 0; s < 2; s++) {
            uint32_t af[2][4], bf[4][4];
            #pragma unroll
            for (int mt = 0; mt < 2; mt++) {
                int row = wm * 32 + mt * 16 + l7 + ((grp & 1) << 3);
                int ch  = s * 2 + (grp >> 1);
                ldm_x4(af[mt], abase + row * 64 + ((ch ^ ((row >> 1) & 3)) << 4));
            }
            #pragma unroll
            for (int nt = 0; nt < 4; nt++) {
                int row = wn * 64 + nt * 16 + l7 + ((grp >> 1) << 3);
                int ch  = s * 2 + (grp & 1);
                ldm_x4(bf[nt], bbase + row * 64 + ((ch ^ ((row >> 1) & 3)) << 4));
            }
            #pragma unroll
            for (int mt = 0; mt < 2; mt++)
                #pragma unroll
                for (int nt = 0; nt < 4; nt++) {
                    mma_f16(acc[mt][nt * 2],     af[mt], &bf[nt][0]);
                    mma_f16(acc[mt][nt * 2 + 1], af[mt], &bf[nt][2]);
                }
        }
    }

    int g8 = lane >> 2, t2 = (lane & 3) * 2;
    #pragma unroll
    for (int mt = 0; mt < 2; mt++) {
        #pragma unroll
        for (int nt = 0; nt < 8; nt++) {
            long long row = m0 + wm * 32 + mt * 16 + g8;
            int col = n0 + wn * 64 + nt * 8 + t2;
            if (HALF_OUT) {
                __half* C = (__half*)Cv;
                *(__half2*)(C + row * ldc + col) =
                    __floats2half2_rn(acc[mt][nt][0], acc[mt][nt][1]);
                *(__half2*)(C + (row + 8) * ldc + col) =
                    __floats2half2_rn(acc[mt][nt][2], acc[mt][nt][3]);
            } else {
                float* C = (float*)Cv;
                *(float2*)(C + row * ldc + col) =
                    make_float2(acc[mt][nt][0], acc[mt][nt][1]);
                *(float2*)(C + (row + 8) * ldc + col) =
                    make_float2(acc[mt][nt][2], acc[mt][nt][3]);
            }
        }
    }
}

template<bool HALF_OUT>
__global__ __launch_bounds__(256, 2) void hgemm_nt(
    const __half* __restrict__ A, const __half* __restrict__ B, void* __restrict__ Cv,
    int K, int lda, int ldb, int ldc)
{
    hgemm_body<HALF_OUT>(A, B, Cv, blockIdx.y * 128, blockIdx.x * 128, K, lda, ldb, ldc);
}

// Combined Q + K + V^T projections in ONE launch (1152 CTAs).
__global__ __launch_bounds__(256, 2) void hgemm_qkv(
    const __half* __restrict__ hs,  const __half* __restrict__ wq,
    const __half* __restrict__ wk,  const __half* __restrict__ wv,
    __half* __restrict__ qout, __half* __restrict__ kout, __half* __restrict__ vtout)
{
    int b = blockIdx.x;
    if (b < 1024) {            // qout = hs @ wq^T   [2048 x 8192]
        hgemm_body<true>(hs, wq, qout, (b >> 6) << 7, (b & 63) << 7,
                         HIDDEN, HIDDEN, HIDDEN, QROW);
    } else if (b < 1088) {     // kout = hs @ wk^T   [2048 x 512]
        int c = b - 1024;
        hgemm_body<true>(hs, wk, kout, (c >> 2) << 7, (c & 3) << 7,
                         HIDDEN, HIDDEN, HIDDEN, KROW);
    } else {                   // vtout = wv @ hs^T  [512 x 2048]
        int c = b - 1088;
        hgemm_body<true>(wv, hs, vtout, (c >> 4) << 7, (c & 15) << 7,
                         HIDDEN, HIDDEN, HIDDEN, SEQ);
    }
}

// ======================= fused flash attention =============================
// CTA: 128 q-rows x 1 head. 8 warps; warp = 16 q-rows x full 256 d.
// k tiles of 64, double-buffered cp.async; online softmax fp32 with exact
// rescale-skip (multiplier == 1 when the running max is unchanged).
static constexpr int FQ_BYTES = 128 * 512;
static constexpr int FK_BYTES = 64 * 512;
static constexpr int FSTAGE   = FK_BYTES + 256 * 128;      // 65536
static constexpr int FSMEM    = FQ_BYTES + 2 * FSTAGE;     // 196608

__global__ __launch_bounds__(256, 1) void flash_attn(
    const __half* __restrict__ Qh, const __half* __restrict__ Kh,
    const __half* __restrict__ Vth, __half* __restrict__ O)
{
    int bx = blockIdx.x;
    int qt = 15 - (bx >> 4);          // heavy q-tiles first
    int h  = bx & 15;
    int q0 = qt << 7;
    int kv = h >> 3;
    int niter = (qt + 1) << 1;

    extern __shared__ char smem[];
    uint32_t sq = smem_u32(smem);

    int tid = threadIdx.x, lane = tid & 31, wid = tid >> 5;
    int grp = lane >> 3, l7 = lane & 7;
    int g8 = lane >> 2, t2 = (lane & 3) << 1;

    #pragma unroll
    for (int i = 0; i < 16; i++) {
        int id = tid + (i << 8);
        int r = id >> 5, c = id & 31;
        CP_ASYNC16(sq + r * 512 + ((c ^ (r & 7)) << 4),
                   Qh + (size_t)(q0 + r) * QROW + h * 512 + c * 8);
    }
    auto fillKV = [&](int it, int st) {
        int k0 = it << 6;
        uint32_t kb = sq + FQ_BYTES + st * FSTAGE;
        uint32_t vb = kb + FK_BYTES;
        #pragma unroll
        for (int i = 0; i < 8; i++) {
            int id = tid + (i << 8);
            int r = id >> 5, c = id & 31;
            CP_ASYNC16(kb + r * 512 + ((c ^ (r & 7)) << 4),
                       Kh + (size_t)(k0 + r) * KROW + kv * 256 + c * 8);
        }
        #pragma unroll
        for (int i = 0; i < 8; i++) {
            int id = tid + (i << 8);
            int d = id >> 3, c = id & 7;
            CP_ASYNC16(vb + d * 128 + ((c ^ (d & 7)) << 4),
                       Vth + (size_t)(kv * 256 + d) * SEQ + k0 + c * 8);
        }
    };
    fillKV(0, 0);
    CP_COMMIT();
    if (niter > 1) { fillKV(1, 1); CP_COMMIT(); }

    float m0 = MASKV, m1 = MASKV, l0 = 0.f, l1 = 0.f;
    float accO[32][4] = {};
    int qrow0 = q0 + wid * 16 + g8;

    for (int it = 0; it < niter; it++) {
        int k0 = it << 6;
        if (it + 1 < niter) { CP_WAIT(1); } else { CP_WAIT(0); }
        __syncthreads();

        uint32_t kb = sq + FQ_BYTES + (it & 1) * FSTAGE;
        uint32_t vb = kb + FK_BYTES;

        // ---- S = Q K^T ----
        float accS[8][4] = {};
        #pragma unroll
        for (int s = 0; s < 16; s++) {
            uint32_t af[4];
            int qr = wid * 16 + l7 + ((grp & 1) << 3);
            int ch = s * 2 + (grp >> 1);
            ldm_x4(af, sq + qr * 512 + ((ch ^ (qr & 7)) << 4));
            #pragma unroll
            for (int np = 0; np < 4; np++) {
                uint32_t bf[4];
                int kr = np * 16 + l7 + ((grp >> 1) << 3);
                int c2 = s * 2 + (grp & 1);
                ldm_x4(bf, kb + kr * 512 + ((c2 ^ (kr & 7)) << 4));
                mma_f16(accS[np * 2],     af, &bf[0]);
                mma_f16(accS[np * 2 + 1], af, &bf[2]);
            }
        }
        #pragma unroll
        for (int nt = 0; nt < 8; nt++)
            #pragma unroll
            for (int q = 0; q < 4; q++) accS[nt][q] *= ATTN_SCALE;

        if (k0 + 63 > q0 + wid * 16) {       // causal mask (diagonal tiles)
            #pragma unroll
            for (int nt = 0; nt < 8; nt++) {
                int c0 = k0 + nt * 8 + t2;
                if (c0 > qrow0)         accS[nt][0] = MASKV;
                if (c0 + 1 > qrow0)     accS[nt][1] = MASKV;
                if (c0 > qrow0 + 8)     accS[nt][2] = MASKV;
                if (c0 + 1 > qrow0 + 8) accS[nt][3] = MASKV;
            }
        }

        // ---- online softmax ----
        float mx0 = MASKV, mx1 = MASKV;
        #pragma unroll
        for (int nt = 0; nt < 8; nt++) {
            mx0 = fmaxf(mx0, fmaxf(accS[nt][0], accS[nt][1]));
            mx1 = fmaxf(mx1, fmaxf(accS[nt][2], accS[nt][3]));
        }
        mx0 = fmaxf(mx0, __shfl_xor_sync(0xffffffffu, mx0, 1));
        mx0 = fmaxf(mx0, __shfl_xor_sync(0xffffffffu, mx0, 2));
        mx1 = fmaxf(mx1, __shfl_xor_sync(0xffffffffu, mx1, 1));
        mx1 = fmaxf(mx1, __shfl_xor_sync(0xffffffffu, mx1, 2));

        float mn0 = fmaxf(m0, mx0), mn1 = fmaxf(m1, mx1);
        int need = __any_sync(0xffffffffu, (mn0 != m0) || (mn1 != m1));
        float a0 = __expf(m0 - mn0), a1 = __expf(m1 - mn1);
        m0 = mn0; m1 = mn1;
        float s0 = 0.f, s1 = 0.f;
        #pragma unroll
        for (int nt = 0; nt < 8; nt++) {
            accS[nt][0] = __expf(accS[nt][0] - mn0); s0 += accS[nt][0];
            accS[nt][1] = __expf(accS[nt][1] - mn0); s0 += accS[nt][1];
            accS[nt][2] = __expf(accS[nt][2] - mn1); s1 += accS[nt][2];
            accS[nt][3] = __expf(accS[nt][3] - mn1); s1 += accS[nt][3];
        }
        s0 += __shfl_xor_sync(0xffffffffu, s0, 1);
        s0 += __shfl_xor_sync(0xffffffffu, s0, 2);
        s1 += __shfl_xor_sync(0xffffffffu, s1, 1);
        s1 += __shfl_xor_sync(0xffffffffu, s1, 2);
        l0 = l0 * a0 + s0;
        l1 = l1 * a1 + s1;
        if (need) {   // exact skip: a == 1 for every row when no max changed
            #pragma unroll
            for (int nt = 0; nt < 32; nt++) {
                accO[nt][0] *= a0; accO[nt][1] *= a0;
                accO[nt][2] *= a1; accO[nt][3] *= a1;
            }
        }

        // ---- P fragments (S accum layout == A operand layout) ----
        uint32_t pf[4][4];
        #pragma unroll
        for (int kc = 0; kc < 4; kc++) {
            pf[kc][0] = h2u(__floats2half2_rn(accS[2 * kc][0],     accS[2 * kc][1]));
            pf[kc][1] = h2u(__floats2half2_rn(accS[2 * kc][2],     accS[2 * kc][3]));
            pf[kc][2] = h2u(__floats2half2_rn(accS[2 * kc + 1][0], accS[2 * kc + 1][1]));
            pf[kc][3] = h2u(__floats2half2_rn(accS[2 * kc + 1][2], accS[2 * kc + 1][3]));
        }

        // ---- O += P V ----
        #pragma unroll
        for (int np = 0; np < 16; np++) {
            #pragma unroll
            for (int kc = 0; kc < 4; kc++) {
                uint32_t bf[4];
                int dr = np * 16 + l7 + ((grp >> 1) << 3);
                int ch = kc * 2 + (grp & 1);
                ldm_x4(bf, vb + dr * 128 + ((ch ^ (dr & 7)) << 4));
                mma_f16(accO[np * 2],     pf[kc], &bf[0]);
                mma_f16(accO[np * 2 + 1], pf[kc], &bf[2]);
            }
        }

        __syncthreads();
        if (it + 2 < niter) { fillKV(it + 2, it & 1); CP_COMMIT(); }
    }

    // ---- epilogue: 1/l, sigmoid gate, fp16 store ----
    float r0 = 1.f / l0, r1 = 1.f / l1;
    int trow0 = qrow0, trow1 = qrow0 + 8;
    const __half* G0 = Qh + (size_t)trow0 * QROW + h * 512 + 256;
    const __half* G1 = Qh + (size_t)trow1 * QROW + h * 512 + 256;
    __half* O0 = O + (size_t)trow0 * ODIM + h * 256;
    __half* O1 = O + (size_t)trow1 * ODIM + h * 256;
    #pragma unroll
    for (int nt = 0; nt < 32; nt++) {
        int d = nt * 8 + t2;
        float2 ga = __half22float2(*(const __half2*)(G0 + d));
        float2 gb = __half22float2(*(const __half2*)(G1 + d));
        float vx = accO[nt][0] * r0 / (1.f + __expf(-ga.x));
        float vy = accO[nt][1] * r0 / (1.f + __expf(-ga.y));
        float wx = accO[nt][2] * r1 / (1.f + __expf(-gb.x));
        float wy = accO[nt][3] * r1 / (1.f + __expf(-gb.y));
        *(__half2*)(O0 + d) = __floats2half2_rn(vx, vy);
        *(__half2*)(O1 + d) = __floats2half2_rn(wx, wy);
    }
}

// ============================ elementwise kernels ==========================
// One launch converting all five fp32 buffers to fp16.
static constexpr long long F2H_N0 = (long long)SEQ * HIDDEN;     //  4.19M
static constexpr long long F2H_N1 = (long long)QROW * HIDDEN;    // 16.78M
static constexpr long long F2H_N2 = (long long)KROW * HIDDEN;    //  1.05M
static constexpr long long F2H_N3 = (long long)KROW * HIDDEN;
static constexpr long long F2H_N4 = (long long)HIDDEN * ODIM;    //  8.39M
static constexpr long long F2H_TOT = F2H_N0 + F2H_N1 + F2H_N2 + F2H_N3 + F2H_N4;

__global__ __launch_bounds__(256) void f2h_all(
    const float* __restrict__ s0, __half* __restrict__ d0,
    const float* __restrict__ s1, __half* __restrict__ d1,
    const float* __restrict__ s2, __half* __restrict__ d2,
    const float* __restrict__ s3, __half* __restrict__ d3,
    const float* __restrict__ s4, __half* __restrict__ d4)
{
    long long i = ((long long)blockIdx.x * 256 + threadIdx.x) * 4;
    if (i >= F2H_TOT) return;
    const float* s;
    __half* d;
    if (i < F2H_N0)                    { s = s0; d = d0; }
    else if ((i -= F2H_N0) < F2H_N1)   { s = s1; d = d1; }
    else if ((i -= F2H_N1) < F2H_N2)   { s = s2; d = d2; }
    else if ((i -= F2H_N2) < F2H_N3)   { s = s3; d = d3; }
    else { i -= F2H_N3;                  s = s4; d = d4; }
    float4 v = *reinterpret_cast<const float4*>(s + i);
    *reinterpret_cast<__half2*>(d + i)     = __floats2half2_rn(v.x, v.y);
    *reinterpret_cast<__half2*>(d + i + 2) = __floats2half2_rn(v.z, v.w);
}

// Warp-per-row RMSNorm + RoPE on fp16 rows; q-rows and k-rows in one launch.
__global__ __launch_bounds__(256) void rmsnorm_rope_h(
    __half* __restrict__ xq, const float* __restrict__ wq,
    __half* __restrict__ xk, const float* __restrict__ wk,
    const int* __restrict__ pos)
{
    int widx = threadIdx.x >> 5, lane = threadIdx.x & 31;
    int ridx = blockIdx.x * 8 + widx;
    __half* row;
    const float* w;
    int t;
    if (ridx < SEQ * NHEAD) {
        t = ridx >> 4;
        int h = ridx & 15;
        row = xq + (size_t)t * QROW + (size_t)h * 512;
        w = wq;
    } else {
        int r2 = ridx - SEQ * NHEAD;
        t = r2 >> 1;
        int h = r2 & 1;
        row = xk + (size_t)t * KROW + (size_t)h * HD;
        w = wk;
    }

    uint4 raw = *reinterpret_cast<const uint4*>(row + lane * 8);
    __half2 hv[4];
    *reinterpret_cast<uint4*>(hv) = raw;
    float v[8];
    #pragma unroll
    for (int j = 0; j < 4; j++) {
        float2 f = __half22float2(hv[j]);
        v[2 * j] = f.x; v[2 * j + 1] = f.y;
    }
    float s = 0.f;
    #pragma unroll
    for (int j = 0; j < 8; j++) s += v[j] * v[j];
    #pragma unroll
    for (int o = 16; o; o >>= 1) s += __shfl_xor_sync(0xffffffffu, s, o);
    float rinv = rsqrtf(s * (1.0f / 256.0f) + 1e-6f);

    float4 w1 = *reinterpret_cast<const float4*>(w + lane * 8);
    float4 w2 = *reinterpret_cast<const float4*>(w + lane * 8 + 4);
    float y[8] = { v[0] * rinv * (1.0f + w1.x), v[1] * rinv * (1.0f + w1.y),
                   v[2] * rinv * (1.0f + w1.z), v[3] * rinv * (1.0f + w1.w),
                   v[4] * rinv * (1.0f + w2.x), v[5] * rinv * (1.0f + w2.y),
                   v[6] * rinv * (1.0f + w2.z), v[7] * rinv * (1.0f + w2.w) };

    float oth[8];
    #pragma unroll
    for (int j = 0; j < 8; j++) oth[j] = __shfl_xor_sync(0xffffffffu, y[j], 4);
    if (lane < 8) {
        float p = (float)pos[t];
        #pragma unroll
        for (int j = 0; j < 8; j++) {
            int d = lane * 8 + j;
            int fi = d & 31;
            float inv = expf(-(float)fi * (16.118095650958322f / 32.0f));
            float sn, cs;
            sincosf(p * inv, &sn, &cs);
            if (lane < 4) y[j] = y[j] * cs - oth[j] * sn;
            else          y[j] = y[j] * cs + oth[j] * sn;
        }
    }
    #pragma unroll
    for (int j = 0; j < 4; j++) hv[j] = __floats2half2_rn(y[2 * j], y[2 * j + 1]);
    *reinterpret_cast<uint4*>(row + lane * 8) = *reinterpret_cast<uint4*>(hv);
}

// ============================ host launch ==================================
extern "C" void kernel_launch(void* const* d_in, const int* in_sizes, int n_in,
                              void* d_out, int out_size)
{
    const int*   positions = (const int*)d_in[0];
    const float* hs  = (const float*)d_in[1];
    const float* wq  = (const float*)d_in[2];
    const float* wk  = (const float*)d_in[3];
    const float* wv  = (const float*)d_in[4];
    const float* wo  = (const float*)d_in[5];
    const float* qnw = (const float*)d_in[6];
    const float* knw = (const float*)d_in[7];
    float* out = (float*)d_out;

    __half *hhs, *hwq, *hwk, *hwv, *hwo, *hq, *hk, *hvt, *ho;
    cudaGetSymbolAddress((void**)&hhs, g_hs_h);
    cudaGetSymbolAddress((void**)&hwq, g_wq_h);
    cudaGetSymbolAddress((void**)&hwk, g_wk_h);
    cudaGetSymbolAddress((void**)&hwv, g_wv_h);
    cudaGetSymbolAddress((void**)&hwo, g_wo_h);
    cudaGetSymbolAddress((void**)&hq,  g_qout_h);
    cudaGetSymbolAddress((void**)&hk,  g_kbuf_h);
    cudaGetSymbolAddress((void**)&hvt, g_vt_h);
    cudaGetSymbolAddress((void**)&ho,  g_obuf_h);

    cudaFuncSetAttribute(hgemm_nt<false>,
                         cudaFuncAttributeMaxDynamicSharedMemorySize, SMEM_BYTES);
    cudaFuncSetAttribute(hgemm_qkv,
                         cudaFuncAttributeMaxDynamicSharedMemorySize, SMEM_BYTES);
    cudaFuncSetAttribute(flash_attn,
                         cudaFuncAttributeMaxDynamicSharedMemorySize, FSMEM);

    dim3 blk(256);

    // 0) fp32 -> fp16 (single launch, all five buffers)
    f2h_all<<<(int)((F2H_TOT / 4 + 255) / 256), 256>>>(
        hs, hhs, wq, hwq, wk, hwk, wv, hwv, wo, hwo);

    // 1) Q + K + V^T projections (one launch, 1152 CTAs)
    hgemm_qkv<<<1152, blk, SMEM_BYTES>>>(hhs, hwq, hwk, hwv, hq, hk, hvt);

    // 2) RMSNorm + RoPE (q rows + k rows, one launch)
    rmsnorm_rope_h<<<(SEQ * NHEAD + SEQ * NKV) / 8, 256>>>(
        hq, qnw, hk, knw, positions);

    // 3) Fused flash attention (scores + softmax + PV + gate)
    flash_attn<<<256, blk, FSMEM>>>(hq, hk, hvt, ho);

    // 4) Output projection (f32 out): out = ho @ wo^T
    hgemm_nt<false><<<dim3(HIDDEN / 128, SEQ / 128, 1), blk, SMEM_BYTES>>>(
        ho, hwo, out, ODIM, ODIM, ODIM, HIDDEN);
}